// round 4
// baseline (speedup 1.0000x reference)
#include <cuda_runtime.h>
#include <cuda_fp16.h>
#include <stdint.h>

#define T_TOK 32768
#define DIM   1024
#define FF    2048
#define NE    8

#define KC     64          // K halves per chunk (128B)
#define LDP    72          // padded row stride in halves (144B)

// dynamic smem layout (bytes)
#define OFF_TOK   0
#define OFF_GATE  512
#define OFF_A0    1024
#define STAGE_A   (128 * LDP * 2)              // 18432
#define STAGE_SZ  (2 * STAGE_A)                // 36864 (A then B)
#define SMEM_SZ   (OFF_A0 + 2 * STAGE_SZ)      // 74752 -> 2 CTAs/SM

// ---------------- device scratch ----------------
__device__ int    g_counts[NE];
__device__ int    g_offsets[NE];
__device__ int    g_is64;
__device__ int    g_tok [NE * T_TOK];
__device__ float  g_gate[NE * T_TOK];
__device__ __half g_xh [(size_t)T_TOK * DIM];
__device__ __half g_w1h[(size_t)NE * FF * DIM];
__device__ __half g_w2h[(size_t)NE * DIM * FF];
__device__ __half g_h  [(size_t)T_TOK * 2 * FF];

// ---------------- helpers ----------------
__device__ __forceinline__ void cp16s(uint32_t s, const void* g) {
    asm volatile("cp.async.cg.shared.global [%0], [%1], 16;\n" :: "r"(s), "l"(g));
}
#define CP_COMMIT() asm volatile("cp.async.commit_group;\n" ::: "memory")
#define CP_WAIT(n)  asm volatile("cp.async.wait_group %0;\n" :: "n"(n) : "memory")

#define LDSM4(r0, r1, r2, r3, addr) \
    asm volatile("ldmatrix.sync.aligned.m8n8.x4.shared.b16 {%0,%1,%2,%3}, [%4];" \
                 : "=r"(r0), "=r"(r1), "=r"(r2), "=r"(r3) : "r"(addr))

__device__ __forceinline__ void mma16816(float* c, const uint32_t* a, uint32_t b0, uint32_t b1) {
    asm volatile(
        "mma.sync.aligned.m16n8k16.row.col.f32.f16.f16.f32 "
        "{%0,%1,%2,%3}, {%4,%5,%6,%7}, {%8,%9}, {%0,%1,%2,%3};\n"
        : "+f"(c[0]), "+f"(c[1]), "+f"(c[2]), "+f"(c[3])
        : "r"(a[0]), "r"(a[1]), "r"(a[2]), "r"(a[3]), "r"(b0), "r"(b1));
}

__device__ __forceinline__ float silu_f(float v) {
    return v * __frcp_rn(1.0f + __expf(-v));
}

// ---------------- prep kernels ----------------
__global__ void zero_out_kernel(float4* out, int n4) {
    int i = blockIdx.x * blockDim.x + threadIdx.x;
    int stride = gridDim.x * blockDim.x;
    float4 z = make_float4(0.f, 0.f, 0.f, 0.f);
    for (int j = i; j < n4; j += stride) out[j] = z;
    if (i < NE) g_counts[i] = 0;
}

__global__ void convert_kernel(const float* __restrict__ src, __half* __restrict__ dst, int n4) {
    int i = blockIdx.x * blockDim.x + threadIdx.x;
    int stride = gridDim.x * blockDim.x;
    for (int j = i; j < n4; j += stride) {
        float4 v = reinterpret_cast<const float4*>(src)[j];
        reinterpret_cast<__half2*>(dst)[2*j]   = __floats2half2_rn(v.x, v.y);
        reinterpret_cast<__half2*>(dst)[2*j+1] = __floats2half2_rn(v.z, v.w);
    }
}

__global__ void detect_kernel(const int* __restrict__ idx_words) {
    if (blockIdx.x == 0 && threadIdx.x == 0) {
        int is64 = 1;
        for (int i = 1; i < 64; i += 2)
            if (idx_words[i] != 0) { is64 = 0; break; }
        g_is64 = is64;
    }
}

__global__ void route_kernel(const void* __restrict__ idx_raw, const float* __restrict__ probs) {
    int t = blockIdx.x * blockDim.x + threadIdx.x;
    if (t >= T_TOK) return;
    int e0, e1;
    if (g_is64) {
        const long long* p = (const long long*)idx_raw;
        e0 = (int)p[2*t]; e1 = (int)p[2*t+1];
    } else {
        const int* p = (const int*)idx_raw;
        e0 = p[2*t]; e1 = p[2*t+1];
    }
    float p0 = probs[2*t], p1 = probs[2*t+1];
    if (e0 == e1) p0 += p1;
    int pos = atomicAdd(&g_counts[e0], 1);
    g_tok [e0 * T_TOK + pos] = t;
    g_gate[e0 * T_TOK + pos] = p0;
    if (e1 != e0) {
        pos = atomicAdd(&g_counts[e1], 1);
        g_tok [e1 * T_TOK + pos] = t;
        g_gate[e1 * T_TOK + pos] = p1;
    }
}

__global__ void scan_kernel() {
    if (threadIdx.x == 0 && blockIdx.x == 0) {
        int s = 0;
        for (int e = 0; e < NE; e++) { g_offsets[e] = s; s += g_counts[e]; }
    }
}

// ================= GEMM compute chunk =================
// 128x128 tile, 8 warps (warp tile 32x64), KC=64 via 4 k16 steps, ldmatrix frags.
struct GemmCtx {
    uint32_t sb;
    int wm, wn, lane;
};

__device__ __forceinline__ void gemm_compute_chunk(const GemmCtx& c, int st,
                                                   float acc[2][8][4]) {
    const uint32_t Ab = c.sb + OFF_A0 + st * STAGE_SZ;
    const uint32_t Bb = Ab + STAGE_A;
    const int lane15 = c.lane & 15, laneHi = c.lane >> 4;
    const int brow = (c.lane & 7) + ((c.lane >> 4) & 1) * 8;
    const int bcol = ((c.lane >> 3) & 1) * 8;
    #pragma unroll
    for (int kk = 0; kk < 4; kk++) {
        const int kb = kk * 16;
        uint32_t a[2][4];
        #pragma unroll
        for (int mtl = 0; mtl < 2; mtl++) {
            uint32_t addr = Ab + ((c.wm + mtl * 16 + lane15) * LDP + kb + laneHi * 8) * 2;
            LDSM4(a[mtl][0], a[mtl][1], a[mtl][2], a[mtl][3], addr);
        }
        #pragma unroll
        for (int ng = 0; ng < 4; ng++) {
            uint32_t b0, b1, b2, b3;
            uint32_t addr = Bb + ((c.wn + ng * 16 + brow) * LDP + kb + bcol) * 2;
            LDSM4(b0, b1, b2, b3, addr);
            mma16816(acc[0][ng * 2],     a[0], b0, b1);
            mma16816(acc[0][ng * 2 + 1], a[0], b2, b3);
            mma16816(acc[1][ng * 2],     a[1], b0, b1);
            mma16816(acc[1][ng * 2 + 1], a[1], b2, b3);
        }
    }
}

// ---------------- GEMM1: H = silu(X_gather @ W1[e]^T) ----------------
// grid (FF/128, T/128, NE), 256 threads
__global__ void __launch_bounds__(256, 2) moe_gemm1() {
    const int e = blockIdx.z;
    const int count = g_counts[e];
    const int m0 = blockIdx.y * 128;
    if (m0 >= count) return;
    const int n0 = blockIdx.x * 128;

    extern __shared__ char smem[];
    const uint32_t sb = (uint32_t)__cvta_generic_to_shared(smem);
    const int tid = threadIdx.x;
    const int w = tid >> 5, lane = tid & 31;

    int* s_tok = (int*)(smem + OFF_TOK);
    if (tid < 128) {
        int i = m0 + tid;
        s_tok[tid] = g_tok[e * T_TOK + (i < count ? i : count - 1)];
    }
    __syncthreads();

    const __half* wbase = g_w1h + (size_t)e * FF * DIM;
    const int lr = tid >> 1;              // loader row 0..127
    const int lc = (tid & 1) * 32;        // 0 or 32 halves
    const __half* a_g0 = g_xh + (size_t)s_tok[lr] * DIM + lc;
    const __half* b_g0 = wbase + (size_t)(n0 + lr) * DIM + lc;
    const uint32_t s_row = (lr * LDP + lc) * 2;

    auto fill = [&](int st, int kt) {
        uint32_t a_s = sb + OFF_A0 + st * STAGE_SZ + s_row;
        uint32_t b_s = a_s + STAGE_A;
        const __half* a_g = a_g0 + kt * KC;
        const __half* b_g = b_g0 + kt * KC;
        #pragma unroll
        for (int i = 0; i < 4; i++) cp16s(a_s + i * 16, a_g + i * 8);
        #pragma unroll
        for (int i = 0; i < 4; i++) cp16s(b_s + i * 16, b_g + i * 8);
    };

    float acc[2][8][4];
    #pragma unroll
    for (int i = 0; i < 2; i++)
        #pragma unroll
        for (int j = 0; j < 8; j++)
            #pragma unroll
            for (int q = 0; q < 4; q++) acc[i][j][q] = 0.f;

    GemmCtx c; c.sb = sb; c.wm = (w & 3) * 32; c.wn = (w >> 2) * 64; c.lane = lane;

    const int KT = DIM / KC;   // 16
    fill(0, 0); CP_COMMIT();
    for (int kt = 0; kt < KT; kt++) {
        const int s = kt & 1;
        if (kt + 1 < KT) { fill(s ^ 1, kt + 1); CP_COMMIT(); CP_WAIT(1); }
        else             { CP_WAIT(0); }
        __syncthreads();
        gemm_compute_chunk(c, s, acc);
        __syncthreads();
    }

    // epilogue: silu -> fp16 -> g_h
    const int g = lane >> 2, t4 = lane & 3;
    const int hbase = g_offsets[e] + m0;
    #pragma unroll
    for (int mtl = 0; mtl < 2; mtl++) {
        int r0 = c.wm + mtl * 16 + g;
        int r1 = r0 + 8;
        #pragma unroll
        for (int nt = 0; nt < 8; nt++) {
            int col = n0 + c.wn + nt * 8 + t4 * 2;
            if (m0 + r0 < count) {
                __half2 h = __floats2half2_rn(silu_f(acc[mtl][nt][0]), silu_f(acc[mtl][nt][1]));
                *(__half2*)&g_h[(size_t)(hbase + r0) * FF + col] = h;
            }
            if (m0 + r1 < count) {
                __half2 h = __floats2half2_rn(silu_f(acc[mtl][nt][2]), silu_f(acc[mtl][nt][3]));
                *(__half2*)&g_h[(size_t)(hbase + r1) * FF + col] = h;
            }
        }
    }
}

// ---------------- GEMM2: out[tok] += gate * (H @ W2[e]^T) ----------------
// grid (DIM/128, T/128, NE), 256 threads
__global__ void __launch_bounds__(256, 2) moe_gemm2(float* __restrict__ out) {
    const int e = blockIdx.z;
    const int count = g_counts[e];
    const int m0 = blockIdx.y * 128;
    if (m0 >= count) return;
    const int n0 = blockIdx.x * 128;

    extern __shared__ char smem[];
    const uint32_t sb = (uint32_t)__cvta_generic_to_shared(smem);
    const int tid = threadIdx.x;
    const int w = tid >> 5, lane = tid & 31;
    const int offs = g_offsets[e];

    int*   s_tok  = (int*)(smem + OFF_TOK);
    float* s_gate = (float*)(smem + OFF_GATE);
    if (tid < 128) {
        int i = m0 + tid;
        int ic = (i < count) ? i : count - 1;
        s_tok [tid] = g_tok [e * T_TOK + ic];
        s_gate[tid] = g_gate[e * T_TOK + ic];
    }
    __syncthreads();

    const __half* wbase = g_w2h + (size_t)e * DIM * FF;
    const int lr = tid >> 1;
    const int lc = (tid & 1) * 32;
    const int hr = offs + ((m0 + lr < count) ? m0 + lr : count - 1);
    const __half* a_g0 = g_h + (size_t)hr * FF + lc;
    const __half* b_g0 = wbase + (size_t)(n0 + lr) * FF + lc;
    const uint32_t s_row = (lr * LDP + lc) * 2;

    auto fill = [&](int st, int kt) {
        uint32_t a_s = sb + OFF_A0 + st * STAGE_SZ + s_row;
        uint32_t b_s = a_s + STAGE_A;
        const __half* a_g = a_g0 + kt * KC;
        const __half* b_g = b_g0 + kt * KC;
        #pragma unroll
        for (int i = 0; i < 4; i++) cp16s(a_s + i * 16, a_g + i * 8);
        #pragma unroll
        for (int i = 0; i < 4; i++) cp16s(b_s + i * 16, b_g + i * 8);
    };

    float acc[2][8][4];
    #pragma unroll
    for (int i = 0; i < 2; i++)
        #pragma unroll
        for (int j = 0; j < 8; j++)
            #pragma unroll
            for (int q = 0; q < 4; q++) acc[i][j][q] = 0.f;

    GemmCtx c; c.sb = sb; c.wm = (w & 3) * 32; c.wn = (w >> 2) * 64; c.lane = lane;

    const int KT = FF / KC;   // 32
    fill(0, 0); CP_COMMIT();
    for (int kt = 0; kt < KT; kt++) {
        const int s = kt & 1;
        if (kt + 1 < KT) { fill(s ^ 1, kt + 1); CP_COMMIT(); CP_WAIT(1); }
        else             { CP_WAIT(0); }
        __syncthreads();
        gemm_compute_chunk(c, s, acc);
        __syncthreads();
    }

    const int g = lane >> 2, t4 = lane & 3;
    #pragma unroll
    for (int mtl = 0; mtl < 2; mtl++) {
        int r0 = c.wm + mtl * 16 + g;
        int r1 = r0 + 8;
        #pragma unroll
        for (int nt = 0; nt < 8; nt++) {
            int col = n0 + c.wn + nt * 8 + t4 * 2;
            if (m0 + r0 < count) {
                float gate = s_gate[r0];
                float2 v = make_float2(gate * acc[mtl][nt][0], gate * acc[mtl][nt][1]);
                atomicAdd(reinterpret_cast<float2*>(&out[(size_t)s_tok[r0] * DIM + col]), v);
            }
            if (m0 + r1 < count) {
                float gate = s_gate[r1];
                float2 v = make_float2(gate * acc[mtl][nt][2], gate * acc[mtl][nt][3]);
                atomicAdd(reinterpret_cast<float2*>(&out[(size_t)s_tok[r1] * DIM + col]), v);
            }
        }
    }
}

// ---------------- launcher ----------------
extern "C" void kernel_launch(void* const* d_in, const int* in_sizes, int n_in,
                              void* d_out, int out_size) {
    const float* x     = (const float*)d_in[0];
    const float* probs = (const float*)d_in[1];
    const void*  idx   = d_in[2];
    const float* w1    = (const float*)d_in[3];
    const float* w2    = (const float*)d_in[4];
    float* out = (float*)d_out;

    __half *p_xh, *p_w1h, *p_w2h;
    cudaGetSymbolAddress((void**)&p_xh,  g_xh);
    cudaGetSymbolAddress((void**)&p_w1h, g_w1h);
    cudaGetSymbolAddress((void**)&p_w2h, g_w2h);

    static int attr_done = 0;
    if (!attr_done) {
        cudaFuncSetAttribute(moe_gemm1, cudaFuncAttributeMaxDynamicSharedMemorySize, SMEM_SZ);
        cudaFuncSetAttribute(moe_gemm2, cudaFuncAttributeMaxDynamicSharedMemorySize, SMEM_SZ);
        attr_done = 1;
    }

    zero_out_kernel<<<8192, 256>>>((float4*)out, out_size / 4);
    convert_kernel<<<4096, 256>>>(x,  p_xh,  (T_TOK * DIM) / 4);
    convert_kernel<<<4096, 256>>>(w1, p_w1h, (NE * FF * DIM) / 4);
    convert_kernel<<<4096, 256>>>(w2, p_w2h, (NE * DIM * FF) / 4);
    detect_kernel<<<1, 32>>>((const int*)idx);
    route_kernel<<<T_TOK / 256, 256>>>(idx, probs);
    scan_kernel<<<1, 32>>>();

    dim3 g1(FF / 128, T_TOK / 128, NE);
    moe_gemm1<<<g1, 256, SMEM_SZ>>>();
    dim3 g2(DIM / 128, T_TOK / 128, NE);
    moe_gemm2<<<g2, 256, SMEM_SZ>>>(out);
}

// round 7
// speedup vs baseline: 1.1687x; 1.1687x over previous
#include <cuda_runtime.h>
#include <cuda_fp16.h>
#include <stdint.h>

#define T_TOK 32768
#define DIM   1024
#define FF    2048
#define NE    8

// ---------------- device scratch ----------------
__device__ int    g_counts[NE];
__device__ int    g_is64;
__device__ int    g_tok [NE * T_TOK];
__device__ float  g_gate[NE * T_TOK];
__device__ __half g_xh [(size_t)T_TOK * DIM];
__device__ __half g_w1h[(size_t)NE * FF * DIM];
__device__ __half g_w2h[(size_t)NE * DIM * FF];
__device__ __half g_h  [(size_t)T_TOK * 2 * FF];

// ---------------- helpers ----------------
__device__ __forceinline__ void cp16(void* smem, const void* gmem) {
    uint32_t s = (uint32_t)__cvta_generic_to_shared(smem);
    asm volatile("cp.async.cg.shared.global [%0], [%1], 16;\n" :: "r"(s), "l"(gmem));
}
#define CP_COMMIT() asm volatile("cp.async.commit_group;\n" ::: "memory")
#define CP_WAIT(n)  asm volatile("cp.async.wait_group %0;\n" :: "n"(n) : "memory")

__device__ __forceinline__ void mma16816(float* c, const uint32_t* a, uint32_t b0, uint32_t b1) {
    asm volatile(
        "mma.sync.aligned.m16n8k16.row.col.f32.f16.f16.f32 "
        "{%0,%1,%2,%3}, {%4,%5,%6,%7}, {%8,%9}, {%0,%1,%2,%3};\n"
        : "+f"(c[0]), "+f"(c[1]), "+f"(c[2]), "+f"(c[3])
        : "r"(a[0]), "r"(a[1]), "r"(a[2]), "r"(a[3]), "r"(b0), "r"(b1));
}

__device__ __forceinline__ float silu_f(float v) {
    return v * __frcp_rn(1.0f + __expf(-v));
}

// ---------------- prep kernels ----------------
// clears counters + detects int64-vs-int32 index encoding
__global__ void detect_clear_kernel(const int* __restrict__ idx_words) {
    if (threadIdx.x < NE) g_counts[threadIdx.x] = 0;
    if (threadIdx.x == 0) {
        int is64 = 1;
        for (int i = 1; i < 64; i += 2)
            if (idx_words[i] != 0) { is64 = 0; break; }
        g_is64 = is64;
    }
}

// block-aggregated routing: shared counts -> one global atomic per (block, expert)
__global__ void route_kernel(const void* __restrict__ idx_raw, const float* __restrict__ probs) {
    __shared__ int cnt[NE], base[NE];
    const int tid = threadIdx.x;
    const int t = blockIdx.x * 256 + tid;
    if (tid < NE) cnt[tid] = 0;
    __syncthreads();

    int e0, e1;
    if (g_is64) {
        const long long* p = (const long long*)idx_raw;
        e0 = (int)p[2*t]; e1 = (int)p[2*t+1];
    } else {
        const int* p = (const int*)idx_raw;
        e0 = p[2*t]; e1 = p[2*t+1];
    }
    float p0 = probs[2*t], p1 = probs[2*t+1];
    if (e0 == e1) p0 += p1;
    int pos0 = atomicAdd(&cnt[e0], 1);
    int pos1 = (e1 != e0) ? atomicAdd(&cnt[e1], 1) : -1;
    __syncthreads();

    if (tid < NE) base[tid] = atomicAdd(&g_counts[tid], cnt[tid]);
    __syncthreads();

    int i0 = e0 * T_TOK + base[e0] + pos0;
    g_tok[i0] = t; g_gate[i0] = p0;
    if (pos1 >= 0) {
        int i1 = e1 * T_TOK + base[e1] + pos1;
        g_tok[i1] = t; g_gate[i1] = p1;
    }
}

__global__ void zero_out_kernel(float4* out, int n4) {
    int i = blockIdx.x * blockDim.x + threadIdx.x;
    int stride = gridDim.x * blockDim.x;
    float4 z = make_float4(0.f, 0.f, 0.f, 0.f);
    for (int j = i; j < n4; j += stride) out[j] = z;
}

__global__ void convert_kernel(const float* __restrict__ src, __half* __restrict__ dst, int n4) {
    int i = blockIdx.x * blockDim.x + threadIdx.x;
    int stride = gridDim.x * blockDim.x;
    for (int j = i; j < n4; j += stride) {
        float4 v = reinterpret_cast<const float4*>(src)[j];
        reinterpret_cast<__half2*>(dst)[2*j]   = __floats2half2_rn(v.x, v.y);
        reinterpret_cast<__half2*>(dst)[2*j+1] = __floats2half2_rn(v.z, v.w);
    }
}

// ---------------- GEMM1: H = silu(X_gather @ W1[e]^T), fp16 out ----------------
// grid: (FF/128, T/128, NE), 256 threads  [R1-proven core]
__global__ void __launch_bounds__(256, 2) moe_gemm1() {
    const int e = blockIdx.z;
    const int tid = threadIdx.x;

    __shared__ int s_cnt[NE];
    if (tid < NE) s_cnt[tid] = g_counts[tid];
    __syncthreads();
    const int count = s_cnt[e];
    int offs = 0;
    #pragma unroll
    for (int i = 0; i < NE; i++) offs += (i < e) ? s_cnt[i] : 0;

    const int m0 = blockIdx.y * 128;
    if (m0 >= count) return;
    const int n0 = blockIdx.x * 128;

    __shared__ __half As[2][128 * 40];
    __shared__ __half Bs[2][128 * 40];
    __shared__ int s_tok[128];

    if (tid < 128) {
        int i = m0 + tid;
        s_tok[tid] = g_tok[e * T_TOK + ((i < count) ? i : (count - 1))];
    }
    __syncthreads();

    const int w = tid >> 5, lane = tid & 31;
    const int wm = (w & 3) * 32, wn = (w >> 2) * 64;
    const int g = lane >> 2, t4 = lane & 3;

    float acc[2][8][4];
    #pragma unroll
    for (int i = 0; i < 2; i++)
        #pragma unroll
        for (int j = 0; j < 8; j++)
            #pragma unroll
            for (int q = 0; q < 4; q++) acc[i][j][q] = 0.f;

    const int row_l = tid >> 2;
    const int colh  = (tid & 3) * 8;

    #pragma unroll
    for (int u = 0; u < 2; u++) {
        int row = row_l + u * 64;
        cp16(&As[0][row * 40 + colh], g_xh  + (size_t)s_tok[row] * DIM + colh);
        cp16(&Bs[0][row * 40 + colh], g_w1h + ((size_t)e * FF + n0 + row) * DIM + colh);
    }
    CP_COMMIT();

    const int KT = DIM / 32;
    for (int kt = 0; kt < KT; kt++) {
        if (kt + 1 < KT) {
            int s = (kt + 1) & 1, k0 = (kt + 1) * 32;
            #pragma unroll
            for (int u = 0; u < 2; u++) {
                int row = row_l + u * 64;
                cp16(&As[s][row * 40 + colh], g_xh  + (size_t)s_tok[row] * DIM + k0 + colh);
                cp16(&Bs[s][row * 40 + colh], g_w1h + ((size_t)e * FF + n0 + row) * DIM + k0 + colh);
            }
            CP_COMMIT();
            CP_WAIT(1);
        } else {
            CP_WAIT(0);
        }
        __syncthreads();
        const int s = kt & 1;
        #pragma unroll
        for (int kk = 0; kk < 2; kk++) {
            const int kb = kk * 16 + t4 * 2;
            uint32_t a[2][4];
            #pragma unroll
            for (int mtl = 0; mtl < 2; mtl++) {
                int r0 = wm + mtl * 16 + g;
                const __half* p0 = &As[s][r0 * 40 + kb];
                const __half* p1 = &As[s][(r0 + 8) * 40 + kb];
                a[mtl][0] = *(const uint32_t*)p0;
                a[mtl][1] = *(const uint32_t*)p1;
                a[mtl][2] = *(const uint32_t*)(p0 + 8);
                a[mtl][3] = *(const uint32_t*)(p1 + 8);
            }
            #pragma unroll
            for (int nt = 0; nt < 8; nt++) {
                int n = wn + nt * 8 + g;
                const __half* pb = &Bs[s][n * 40 + kb];
                uint32_t b0 = *(const uint32_t*)pb;
                uint32_t b1 = *(const uint32_t*)(pb + 8);
                #pragma unroll
                for (int mtl = 0; mtl < 2; mtl++)
                    mma16816(acc[mtl][nt], a[mtl], b0, b1);
            }
        }
        __syncthreads();
    }

    const int hbase = offs + m0;
    #pragma unroll
    for (int mtl = 0; mtl < 2; mtl++) {
        int r0 = wm + mtl * 16 + g;
        int r1 = r0 + 8;
        #pragma unroll
        for (int nt = 0; nt < 8; nt++) {
            int col = n0 + wn + nt * 8 + t4 * 2;
            if (m0 + r0 < count) {
                __half2 h = __floats2half2_rn(silu_f(acc[mtl][nt][0]), silu_f(acc[mtl][nt][1]));
                *(__half2*)&g_h[(size_t)(hbase + r0) * FF + col] = h;
            }
            if (m0 + r1 < count) {
                __half2 h = __floats2half2_rn(silu_f(acc[mtl][nt][2]), silu_f(acc[mtl][nt][3]));
                *(__half2*)&g_h[(size_t)(hbase + r1) * FF + col] = h;
            }
        }
    }
}

// ---------------- GEMM2: out[tok] += gate * (H @ W2[e]^T) ----------------
// grid: (DIM/128, T/128, NE), 256 threads  [R1-proven core]
__global__ void __launch_bounds__(256, 2) moe_gemm2(float* __restrict__ out) {
    const int e = blockIdx.z;
    const int tid = threadIdx.x;

    __shared__ int s_cnt[NE];
    if (tid < NE) s_cnt[tid] = g_counts[tid];
    __syncthreads();
    const int count = s_cnt[e];
    int offs = 0;
    #pragma unroll
    for (int i = 0; i < NE; i++) offs += (i < e) ? s_cnt[i] : 0;

    const int m0 = blockIdx.y * 128;
    if (m0 >= count) return;
    const int n0 = blockIdx.x * 128;

    __shared__ __half As[2][128 * 40];
    __shared__ __half Bs[2][128 * 40];
    __shared__ int   s_tok[128];
    __shared__ float s_gate[128];

    if (tid < 128) {
        int i = m0 + tid;
        int ic = (i < count) ? i : (count - 1);
        s_tok [tid] = g_tok [e * T_TOK + ic];
        s_gate[tid] = g_gate[e * T_TOK + ic];
    }
    __syncthreads();

    const int w = tid >> 5, lane = tid & 31;
    const int wm = (w & 3) * 32, wn = (w >> 2) * 64;
    const int g = lane >> 2, t4 = lane & 3;

    float acc[2][8][4];
    #pragma unroll
    for (int i = 0; i < 2; i++)
        #pragma unroll
        for (int j = 0; j < 8; j++)
            #pragma unroll
            for (int q = 0; q < 4; q++) acc[i][j][q] = 0.f;

    const int row_l = tid >> 2;
    const int colh  = (tid & 3) * 8;
    int hrow[2];
    #pragma unroll
    for (int u = 0; u < 2; u++) {
        int i = m0 + row_l + u * 64;
        hrow[u] = offs + ((i < count) ? i : (count - 1));
    }

    #pragma unroll
    for (int u = 0; u < 2; u++) {
        int row = row_l + u * 64;
        cp16(&As[0][row * 40 + colh], g_h   + (size_t)hrow[u] * FF + colh);
        cp16(&Bs[0][row * 40 + colh], g_w2h + ((size_t)e * DIM + n0 + row) * FF + colh);
    }
    CP_COMMIT();

    const int KT = FF / 32;
    for (int kt = 0; kt < KT; kt++) {
        if (kt + 1 < KT) {
            int s = (kt + 1) & 1, k0 = (kt + 1) * 32;
            #pragma unroll
            for (int u = 0; u < 2; u++) {
                int row = row_l + u * 64;
                cp16(&As[s][row * 40 + colh], g_h   + (size_t)hrow[u] * FF + k0 + colh);
                cp16(&Bs[s][row * 40 + colh], g_w2h + ((size_t)e * DIM + n0 + row) * FF + k0 + colh);
            }
            CP_COMMIT();
            CP_WAIT(1);
        } else {
            CP_WAIT(0);
        }
        __syncthreads();
        const int s = kt & 1;
        #pragma unroll
        for (int kk = 0; kk < 2; kk++) {
            const int kb = kk * 16 + t4 * 2;
            uint32_t a[2][4];
            #pragma unroll
            for (int mtl = 0; mtl < 2; mtl++) {
                int r0 = wm + mtl * 16 + g;
                const __half* p0 = &As[s][r0 * 40 + kb];
                const __half* p1 = &As[s][(r0 + 8) * 40 + kb];
                a[mtl][0] = *(const uint32_t*)p0;
                a[mtl][1] = *(const uint32_t*)p1;
                a[mtl][2] = *(const uint32_t*)(p0 + 8);
                a[mtl][3] = *(const uint32_t*)(p1 + 8);
            }
            #pragma unroll
            for (int nt = 0; nt < 8; nt++) {
                int n = wn + nt * 8 + g;
                const __half* pb = &Bs[s][n * 40 + kb];
                uint32_t b0 = *(const uint32_t*)pb;
                uint32_t b1 = *(const uint32_t*)(pb + 8);
                #pragma unroll
                for (int mtl = 0; mtl < 2; mtl++)
                    mma16816(acc[mtl][nt], a[mtl], b0, b1);
            }
        }
        __syncthreads();
    }

    #pragma unroll
    for (int mtl = 0; mtl < 2; mtl++) {
        int r0 = wm + mtl * 16 + g;
        int r1 = r0 + 8;
        #pragma unroll
        for (int nt = 0; nt < 8; nt++) {
            int col = n0 + wn + nt * 8 + t4 * 2;
            if (m0 + r0 < count) {
                float gate = s_gate[r0];
                float2 v = make_float2(gate * acc[mtl][nt][0], gate * acc[mtl][nt][1]);
                atomicAdd(reinterpret_cast<float2*>(&out[(size_t)s_tok[r0] * DIM + col]), v);
            }
            if (m0 + r1 < count) {
                float gate = s_gate[r1];
                float2 v = make_float2(gate * acc[mtl][nt][2], gate * acc[mtl][nt][3]);
                atomicAdd(reinterpret_cast<float2*>(&out[(size_t)s_tok[r1] * DIM + col]), v);
            }
        }
    }
}

// ---------------- launcher ----------------
// Launch order is chosen so ncu (-s 5 -c 1) captures moe_gemm1 as launch #6:
//   1 detect_clear, 2 route, 3 convX, 4 convW1, 5 zero, 6 GEMM1, 7 convW2, 8 GEMM2
extern "C" void kernel_launch(void* const* d_in, const int* in_sizes, int n_in,
                              void* d_out, int out_size) {
    const float* x     = (const float*)d_in[0];
    const float* probs = (const float*)d_in[1];
    const void*  idx   = d_in[2];
    const float* w1    = (const float*)d_in[3];
    const float* w2    = (const float*)d_in[4];
    float* out = (float*)d_out;

    __half *p_xh, *p_w1h, *p_w2h;
    cudaGetSymbolAddress((void**)&p_xh,  g_xh);
    cudaGetSymbolAddress((void**)&p_w1h, g_w1h);
    cudaGetSymbolAddress((void**)&p_w2h, g_w2h);

    detect_clear_kernel<<<1, 32>>>((const int*)idx);
    route_kernel<<<T_TOK / 256, 256>>>(idx, probs);
    convert_kernel<<<4096, 256>>>(x,  p_xh,  (T_TOK * DIM) / 4);
    convert_kernel<<<4096, 256>>>(w1, p_w1h, (NE * FF * DIM) / 4);
    zero_out_kernel<<<8192, 256>>>((float4*)out, out_size / 4);

    dim3 g1(FF / 128, T_TOK / 128, NE);
    moe_gemm1<<<g1, 256>>>();

    convert_kernel<<<4096, 256>>>(w2, p_w2h, (NE * DIM * FF) / 4);

    dim3 g2(DIM / 128, T_TOK / 128, NE);
    moe_gemm2<<<g2, 256>>>(out);
}